// round 13
// baseline (speedup 1.0000x reference)
#include <cuda_runtime.h>
#include <cuda_fp16.h>
#include <cstdint>

#define M_DIM 8192
#define N_DIM 4096
#define K_DIM 4096
#define RANK_K 15099493u   // floor(0.9f * 16777215.0f) in fp32 semantics, frac == 0

// ---------------- device scratch ----------------
__device__ __half    g_X16[(size_t)M_DIM * K_DIM];    // 64 MB  (B operand, row-major m x k)
__device__ __half    g_XT16[(size_t)K_DIM * M_DIM];   // 64 MB  (X^T for correction)
__device__ __half    g_Wc[(size_t)N_DIM * (K_DIM/2)]; // 16 MB  (2:4 packed W, row-major n x k/2)
__device__ unsigned  g_meta[(size_t)N_DIM * 128];     // raw 32b metadata per (row, k32)
__device__ unsigned  g_E[(size_t)256 * 128 * 16];     // mma.sp-arranged metadata
__device__ unsigned  g_ovCnt[(size_t)N_DIM * 128];
__device__ unsigned  g_ovDat[(size_t)N_DIM * 128 * 8];
__device__ unsigned  g_ovRK[(size_t)N_DIM * 64];      // compacted per-row overflow
__device__ unsigned  g_ovRC[N_DIM];
__device__ unsigned  g_hist1[8192];
__device__ unsigned  g_hist2[262144];
__device__ unsigned  g_selP;
__device__ unsigned  g_selBase;
__device__ float     g_thresh;

// ---------------- PTX helpers (base ISA only) ----------------
__device__ __forceinline__ uint32_t smem_u32(const void* p) {
    uint32_t a;
    asm("{ .reg .u64 t; cvta.to.shared.u64 t, %1; cvt.u32.u64 %0, t; }" : "=r"(a) : "l"(p));
    return a;
}
__device__ __forceinline__ void cp16(uint32_t s, const void* g) {
    asm volatile("cp.async.cg.shared.global [%0], [%1], 16;" :: "r"(s), "l"(g));
}
__device__ __forceinline__ void cp_commit() { asm volatile("cp.async.commit_group;" ::: "memory"); }
__device__ __forceinline__ void cp_wait1()  { asm volatile("cp.async.wait_group 1;" ::: "memory"); }

__device__ __forceinline__ void ldsm4(uint32_t& r0, uint32_t& r1, uint32_t& r2, uint32_t& r3,
                                      uint32_t addr) {
    asm volatile("ldmatrix.sync.aligned.m8n8.x4.shared.b16 {%0,%1,%2,%3}, [%4];"
                 : "=r"(r0), "=r"(r1), "=r"(r2), "=r"(r3) : "r"(addr));
}

// 2:4 sparse MMA: D(16x8 f32) = A_sp(16x32 f16, 2:4) * B(32x8 f16) + C
__device__ __forceinline__ void mmasp(float* c, const uint32_t* a,
                                      uint32_t b0, uint32_t b1, uint32_t b2, uint32_t b3,
                                      uint32_t e) {
    asm volatile(
        "mma.sp::ordered_metadata.sync.aligned.m16n8k32.row.col.f32.f16.f16.f32 "
        "{%0,%1,%2,%3}, {%4,%5,%6,%7}, {%8,%9,%10,%11}, {%0,%1,%2,%3}, %12, 0x0;"
        : "+f"(c[0]), "+f"(c[1]), "+f"(c[2]), "+f"(c[3])
        : "r"(a[0]), "r"(a[1]), "r"(a[2]), "r"(a[3]),
          "r"(b0), "r"(b1), "r"(b2), "r"(b3), "r"(e));
}

// ---------------- selection: exact order statistic of |w| bits ----------------
__global__ void zero_kernel() {
    int i = blockIdx.x * blockDim.x + threadIdx.x;
    int st = gridDim.x * blockDim.x;
    for (int j = i; j < 8192; j += st) g_hist1[j] = 0;
    for (int j = i; j < 262144; j += st) g_hist2[j] = 0;
}

__global__ void hist1_kernel(const float4* __restrict__ w, int n4) {
    __shared__ unsigned sh[8192];
    for (int i = threadIdx.x; i < 8192; i += blockDim.x) sh[i] = 0;
    __syncthreads();
    int idx = blockIdx.x * blockDim.x + threadIdx.x;
    int stride = gridDim.x * blockDim.x;
    for (int i = idx; i < n4; i += stride) {
        float4 v = w[i];
        atomicAdd(&sh[(__float_as_uint(v.x) & 0x7FFFFFFFu) >> 18], 1u);
        atomicAdd(&sh[(__float_as_uint(v.y) & 0x7FFFFFFFu) >> 18], 1u);
        atomicAdd(&sh[(__float_as_uint(v.z) & 0x7FFFFFFFu) >> 18], 1u);
        atomicAdd(&sh[(__float_as_uint(v.w) & 0x7FFFFFFFu) >> 18], 1u);
    }
    __syncthreads();
    for (int i = threadIdx.x; i < 8192; i += blockDim.x) {
        unsigned c = sh[i];
        if (c) atomicAdd(&g_hist1[i], c);
    }
}

__global__ void scan1_kernel(unsigned rank) {
    __shared__ unsigned partial[1024];
    int t = threadIdx.x;
    unsigned v[8];
    unsigned s = 0;
#pragma unroll
    for (int i = 0; i < 8; i++) { v[i] = g_hist1[t * 8 + i]; s += v[i]; }
    partial[t] = s;
    __syncthreads();
    for (int ofs = 1; ofs < 1024; ofs <<= 1) {
        unsigned x = (t >= ofs) ? partial[t - ofs] : 0u;
        __syncthreads();
        partial[t] += x;
        __syncthreads();
    }
    unsigned base = partial[t] - s;
    if (rank >= base && rank < partial[t]) {
        unsigned cum = base;
#pragma unroll
        for (int i = 0; i < 8; i++) {
            if (rank < cum + v[i]) { g_selP = (unsigned)(t * 8 + i); g_selBase = cum; break; }
            cum += v[i];
        }
    }
}

__global__ void hist2_kernel(const float4* __restrict__ w, int n4) {
    unsigned P = g_selP;
    int idx = blockIdx.x * blockDim.x + threadIdx.x;
    int stride = gridDim.x * blockDim.x;
    for (int i = idx; i < n4; i += stride) {
        float4 v = w[i];
        unsigned b;
        b = __float_as_uint(v.x) & 0x7FFFFFFFu; if ((b >> 18) == P) atomicAdd(&g_hist2[b & 0x3FFFFu], 1u);
        b = __float_as_uint(v.y) & 0x7FFFFFFFu; if ((b >> 18) == P) atomicAdd(&g_hist2[b & 0x3FFFFu], 1u);
        b = __float_as_uint(v.z) & 0x7FFFFFFFu; if ((b >> 18) == P) atomicAdd(&g_hist2[b & 0x3FFFFu], 1u);
        b = __float_as_uint(v.w) & 0x7FFFFFFFu; if ((b >> 18) == P) atomicAdd(&g_hist2[b & 0x3FFFFu], 1u);
    }
}

__global__ void scan2_kernel(unsigned rank) {
    __shared__ unsigned partial[1024];
    int t = threadIdx.x;
    unsigned s = 0;
    for (int i = 0; i < 256; i++) s += g_hist2[t * 256 + i];
    partial[t] = s;
    __syncthreads();
    for (int ofs = 1; ofs < 1024; ofs <<= 1) {
        unsigned x = (t >= ofs) ? partial[t - ofs] : 0u;
        __syncthreads();
        partial[t] += x;
        __syncthreads();
    }
    unsigned base = partial[t] - s;
    unsigned rl = rank - g_selBase;
    if (rl >= base && rl < partial[t]) {
        unsigned cum = base;
        for (int i = 0; i < 256; i++) {
            unsigned c = g_hist2[t * 256 + i];
            if (rl < cum + c) {
                g_thresh = __uint_as_float((g_selP << 18) | (unsigned)(t * 256 + i));
                break;
            }
            cum += c;
        }
    }
}

// ---------------- X fp16 conversion + transpose ----------------
__global__ void conv_x_kernel(const float4* __restrict__ x, int n4) {
    int idx = blockIdx.x * blockDim.x + threadIdx.x;
    int stride = gridDim.x * blockDim.x;
    uint2* out = reinterpret_cast<uint2*>(g_X16);
    for (int i = idx; i < n4; i += stride) {
        float4 v = x[i];
        __half2 h0 = __floats2half2_rn(v.x, v.y);
        __half2 h1 = __floats2half2_rn(v.z, v.w);
        uint2 o;
        o.x = *reinterpret_cast<unsigned*>(&h0);
        o.y = *reinterpret_cast<unsigned*>(&h1);
        out[i] = o;
    }
}

__global__ void transpose_x_kernel() {
    __shared__ __half t[64][66];
    int bm = blockIdx.x % (M_DIM / 64);
    int bk = blockIdx.x / (M_DIM / 64);
    int m0 = bm * 64, k0 = bk * 64;
    int tid = threadIdx.x;
#pragma unroll
    for (int i = 0; i < 16; i++) {
        int idx = tid + i * 256;
        int mi = idx >> 6, ki = idx & 63;
        t[mi][ki] = g_X16[(size_t)(m0 + mi) * K_DIM + k0 + ki];
    }
    __syncthreads();
#pragma unroll
    for (int i = 0; i < 16; i++) {
        int idx = tid + i * 256;
        int ki = idx >> 6, mi = idx & 63;
        g_XT16[(size_t)(k0 + ki) * M_DIM + m0 + mi] = t[mi][ki];
    }
}

// ---------------- W: threshold mask + 2:4 pack + metadata + overflow ----------------
__global__ void pack_w_kernel(const float* __restrict__ W) {
    int idx = blockIdx.x * 256 + threadIdx.x;      // (r, kb32): 4096*128
    if (idx >= N_DIM * 128) return;
    int r = idx >> 7, kb = idx & 127;
    float t = g_thresh;
    const float4* src = reinterpret_cast<const float4*>(W + (size_t)r * K_DIM + kb * 32);
    unsigned meta = 0, ovc = 0;
    unsigned ovp[8];
    __half st[16];
#pragma unroll
    for (int g = 0; g < 8; g++) {
        float4 v4 = src[g];
        float vv[4] = {v4.x, v4.y, v4.z, v4.w};
        int kept[4], cnt = 0;
#pragma unroll
        for (int j = 0; j < 4; j++) if (fabsf(vv[j]) >= t) kept[cnt++] = j;
        int i0, i1;
        if (cnt == 0)      { i0 = 0; i1 = 1; }
        else if (cnt == 1) { int p = kept[0]; if (p < 3) { i0 = p; i1 = 3; } else { i0 = 2; i1 = 3; } }
        else               { i0 = kept[0]; i1 = kept[1]; }
        float s0 = (fabsf(vv[i0]) >= t) ? vv[i0] : 0.0f;
        float s1 = (fabsf(vv[i1]) >= t) ? vv[i1] : 0.0f;
        st[2 * g]     = __float2half_rn(s0);
        st[2 * g + 1] = __float2half_rn(s1);
        meta |= ((unsigned)(i0 | (i1 << 2))) << (4 * g);
        for (int e = 2; e < cnt; e++) {
            int p = kept[e];
            if (ovc < 8) {
                unsigned hb = (unsigned)__half_as_ushort(__float2half_rn(vv[p]));
                ovp[ovc++] = ((unsigned)(kb * 32 + 4 * g + p) << 16) | hb;
            }
        }
    }
    uint4* dst = reinterpret_cast<uint4*>(g_Wc + (size_t)r * (K_DIM / 2) + kb * 16);
    dst[0] = *reinterpret_cast<uint4*>(&st[0]);
    dst[1] = *reinterpret_cast<uint4*>(&st[8]);
    g_meta[idx] = meta;
    g_ovCnt[idx] = ovc;
    for (unsigned j = 0; j < ovc; j++) g_ovDat[(size_t)idx * 8 + j] = ovp[j];
}

// Arrange metadata into mma.sp thread layout (validated in R12).
__global__ void build_e_kernel() {
    int idx = blockIdx.x * 256 + threadIdx.x;
    if (idx >= 256 * 128 * 16) return;
    int t  = idx & 1;
    int q  = (idx >> 1) & 7;
    int kb = (idx >> 4) & 127;
    int n16 = idx >> 11;
    int r0 = n16 * 16 + q;
    unsigned m0v = g_meta[r0 * 128 + kb];
    unsigned m1v = g_meta[(r0 + 8) * 128 + kb];
    g_E[idx] = t ? ((m0v >> 16) | (m1v & 0xFFFF0000u))
                 : ((m0v & 0xFFFFu) | (m1v << 16));
}

__global__ void compact_ov_kernel() {
    int r = blockIdx.x * 256 + threadIdx.x;
    if (r >= N_DIM) return;
    unsigned c = 0;
    for (int kb = 0; kb < 128; kb++) {
        unsigned n = g_ovCnt[r * 128 + kb];
        for (unsigned j = 0; j < n && c < 64; j++)
            g_ovRK[(size_t)r * 64 + c++] = g_ovDat[((size_t)r * 128 + kb) * 8 + j];
    }
    g_ovRC[r] = c;
}

// ---- Sparse GEMM: A = Wc (2:4, n x k), B = X (m x k, K-contiguous). D = out^T tile. ----
#define NKI 32
#define SA_BYTES 16384
#define SB_BYTES 32768
#define SE_BYTES 2048
#define STAGE_SP (SA_BYTES + SB_BYTES + SE_BYTES)   // 51200
#define SMEM_SP (2 * STAGE_SP)                      // 102400 (>= 128*132*4 = 67584 for sD)

__device__ __forceinline__ void load_stage_sp(uint32_t st, int n0, int m0, int ki, int tid) {
    uint32_t sA = st, sB = st + SA_BYTES, sE = st + SA_BYTES + SB_BYTES;
    const __half* Ap = g_Wc + (size_t)n0 * (K_DIM / 2) + ki * 64;
    const __half* Bp = g_X16 + (size_t)m0 * K_DIM + ki * 128;
#pragma unroll
    for (int i = 0; i < 8; i++) {
        int c = tid + i * 128;
        int row = c >> 3, ci = c & 7;
        cp16(sA + row * 128 + ((ci ^ (row & 7)) << 4), Ap + (size_t)row * (K_DIM / 2) + ci * 8);
    }
#pragma unroll
    for (int i = 0; i < 16; i++) {
        int c = tid + i * 128;
        int row = c >> 4, ci = c & 15;
        cp16(sB + row * 256 + ((ci >> 3) << 7) + (((ci & 7) ^ (row & 7)) << 4),
             Bp + (size_t)row * K_DIM + ci * 8);
    }
    {
        int lt = tid >> 4, rest = tid & 15;
        int kbl = rest >> 2, part = rest & 3;
        size_t src = ((size_t)(n0 / 16 + lt) * 128 + (ki * 4 + kbl)) * 16 + part * 4;
        cp16(sE + ((lt * 4 + kbl) * 16 + part * 4) * 4, g_E + src);
    }
}

__global__ void __launch_bounds__(128, 2) gemm_sp_kernel(const float* __restrict__ bias,
                                                         float* __restrict__ out) {
    extern __shared__ char smraw[];
    const uint32_t sbase = smem_u32(smraw);
    const int tid = threadIdx.x;
    const int wid = tid >> 5;
    const int lane = tid & 31;
    const int wnp = wid >> 1;        // n-dir warp: 0..1 (64 rows)
    const int wmp = wid & 1;         // m-dir warp: 0..1 (64 cols)
    const int m0 = blockIdx.x * 128;
    const int n0 = blockIdx.y * 128;

    float acc[4][8][4];
#pragma unroll
    for (int i = 0; i < 4; i++)
#pragma unroll
        for (int j = 0; j < 8; j++)
#pragma unroll
            for (int k = 0; k < 4; k++) acc[i][j][k] = 0.0f;

    const int g   = lane >> 3;
    const int lr  = lane & 7;
    const int r16 = ((g & 1) << 3) + lr;
    const int kg  = g >> 1;
    const int q   = lane >> 2;
    const int tsel = lane & 1;

    load_stage_sp(sbase, n0, m0, 0, tid); cp_commit();

    for (int ki = 0; ki < NKI; ki++) {
        if (ki + 1 < NKI) load_stage_sp(sbase + ((ki + 1) & 1) * STAGE_SP, n0, m0, ki + 1, tid);
        cp_commit();
        cp_wait1();
        __syncthreads();

        const uint32_t sA = sbase + (uint32_t)(ki & 1) * STAGE_SP;
        const uint32_t sB = sA + SA_BYTES;
        const uint32_t sE = sA + SA_BYTES + SB_BYTES;

#pragma unroll
        for (int kbl = 0; kbl < 4; kbl++) {
            uint32_t a[4][4], b1[4][4], b2[4][4], ev[4];
#pragma unroll
            for (int mt = 0; mt < 4; mt++) {
                int row = wnp * 64 + mt * 16 + r16;
                int cA = kbl * 2 + kg;
                ldsm4(a[mt][0], a[mt][1], a[mt][2], a[mt][3],
                      sA + row * 128 + ((cA ^ (row & 7)) << 4));
            }
#pragma unroll
            for (int bt = 0; bt < 4; bt++) {
                int row = wmp * 64 + bt * 16 + r16;
                int c1 = kbl * 4 + kg;
                int c2 = kbl * 4 + 2 + kg;
                ldsm4(b1[bt][0], b1[bt][1], b1[bt][2], b1[bt][3],
                      sB + row * 256 + ((c1 >> 3) << 7) + (((c1 & 7) ^ (row & 7)) << 4));
                ldsm4(b2[bt][0], b2[bt][1], b2[bt][2], b2[bt][3],
                      sB + row * 256 + ((c2 >> 3) << 7) + (((c2 & 7) ^ (row & 7)) << 4));
            }
#pragma unroll
            for (int mt = 0; mt < 4; mt++) {
                int lt = wnp * 4 + mt;
                uint32_t ea;
                asm volatile("ld.shared.b32 %0, [%1];" : "=r"(ea)
                             : "r"(sE + (uint32_t)(((lt * 4 + kbl) * 16 + q * 2 + tsel) * 4)));
                ev[mt] = ea;
            }
#pragma unroll
            for (int mt = 0; mt < 4; mt++)
#pragma unroll
                for (int bt = 0; bt < 4; bt++)
#pragma unroll
                    for (int od = 0; od < 2; od++)
                        mmasp(acc[mt][bt * 2 + od], a[mt],
                              b1[bt][od], b1[bt][2 + od], b2[bt][od], b2[bt][2 + od],
                              ev[mt]);
        }
        __syncthreads();
    }

    // ---- epilogue: stage D^T through smem, then coalesced row stores ----
    // sD layout: [m_local][n_local], padded row of 132 floats (conflict-free both phases)
    float* sD = reinterpret_cast<float*>(smraw);
    const int c2l = (lane & 3) * 2;
#pragma unroll
    for (int mt = 0; mt < 4; mt++) {
        int nl = wnp * 64 + mt * 16 + q;
#pragma unroll
        for (int nt = 0; nt < 8; nt++) {
            int ml = wmp * 64 + nt * 8 + c2l;
            sD[ml * 132 + nl]           = acc[mt][nt][0];
            sD[(ml + 1) * 132 + nl]     = acc[mt][nt][1];
            sD[ml * 132 + nl + 8]       = acc[mt][nt][2];
            sD[(ml + 1) * 132 + nl + 8] = acc[mt][nt][3];
        }
    }
    __syncthreads();

    // each warp streams 32 m-rows; lanes cover 128 n as float4 -> fully coalesced
    float4 bb = *reinterpret_cast<const float4*>(bias + n0 + lane * 4);
#pragma unroll 4
    for (int r = 0; r < 32; r++) {
        int ml = wid * 32 + r;
        float4 v = *reinterpret_cast<const float4*>(&sD[ml * 132 + lane * 4]);
        v.x += bb.x; v.y += bb.y; v.z += bb.z; v.w += bb.w;
        *reinterpret_cast<float4*>(out + (size_t)(m0 + ml) * N_DIM + n0 + lane * 4) = v;
    }
}

// ---- correction: out[m][n] += sum_overflow w * X[m][k]  (exact remainder) ----
__global__ void corr_kernel(float* __restrict__ out) {
    int m = blockIdx.x * 128 + threadIdx.x;
    int nb = blockIdx.y * 32;
    float accv[32];
#pragma unroll
    for (int i = 0; i < 32; i++) accv[i] = 0.0f;
    unsigned any = 0;
#pragma unroll 1
    for (int rr = 0; rr < 32; rr++) {
        int r = nb + rr;
        unsigned c = g_ovRC[r];
        any |= c;
        for (unsigned j = 0; j < c; j++) {
            unsigned u = g_ovRK[(size_t)r * 64 + j];
            int k = u >> 16;
            float w = __half2float(__ushort_as_half((unsigned short)(u & 0xFFFFu)));
            accv[rr] += w * __half2float(g_XT16[(size_t)k * M_DIM + m]);
        }
    }
    if (any) {
        float4* o = reinterpret_cast<float4*>(out + (size_t)m * N_DIM + nb);
#pragma unroll
        for (int i = 0; i < 8; i++) {
            float4 v = o[i];
            v.x += accv[4 * i + 0]; v.y += accv[4 * i + 1];
            v.z += accv[4 * i + 2]; v.w += accv[4 * i + 3];
            o[i] = v;
        }
    }
}

// ---------------- launch ----------------
extern "C" void kernel_launch(void* const* d_in, const int* in_sizes, int n_in,
                              void* d_out, int out_size) {
    (void)in_sizes; (void)n_in; (void)out_size;
    const float4* x4 = reinterpret_cast<const float4*>(d_in[0]);
    const float*  w  = reinterpret_cast<const float*>(d_in[1]);
    const float4* w4 = reinterpret_cast<const float4*>(d_in[1]);
    const float*  bias = reinterpret_cast<const float*>(d_in[2]);
    float* out = reinterpret_cast<float*>(d_out);

    const int NW4 = (N_DIM * K_DIM) / 4;
    const int NX4 = (M_DIM * K_DIM) / 4;

    cudaFuncSetAttribute(gemm_sp_kernel, cudaFuncAttributeMaxDynamicSharedMemorySize, SMEM_SP);

    zero_kernel<<<512, 256>>>();
    hist1_kernel<<<1184, 256>>>(w4, NW4);
    scan1_kernel<<<1, 1024>>>(RANK_K);
    hist2_kernel<<<1184, 256>>>(w4, NW4);
    scan2_kernel<<<1, 1024>>>(RANK_K);
    conv_x_kernel<<<1184, 256>>>(x4, NX4);
    transpose_x_kernel<<<(M_DIM / 64) * (K_DIM / 64), 256>>>();
    pack_w_kernel<<<(N_DIM * 128) / 256, 256>>>(w);
    build_e_kernel<<<(256 * 128 * 16) / 256, 256>>>();
    compact_ov_kernel<<<N_DIM / 256, 256>>>();
    gemm_sp_kernel<<<dim3(M_DIM / 128, N_DIM / 128), 128, SMEM_SP>>>(bias, out);
    corr_kernel<<<dim3(M_DIM / 128, N_DIM / 32), 128>>>(out);
}

// round 14
// speedup vs baseline: 1.4572x; 1.4572x over previous
#include <cuda_runtime.h>
#include <cuda_fp16.h>
#include <cstdint>

#define M_DIM 8192
#define N_DIM 4096
#define K_DIM 4096
#define RANK_K 15099493u   // floor(0.9f * 16777215.0f) in fp32 semantics, frac == 0

// ---------------- device scratch (static globals: allowed) ----------------
__device__ __half   g_X16[(size_t)M_DIM * K_DIM];   // 64 MB
__device__ __half   g_W16[(size_t)N_DIM * K_DIM];   // 32 MB
__device__ unsigned g_hist1[8192];
__device__ unsigned g_hist2[262144];
__device__ unsigned g_selP;
__device__ unsigned g_selBase;
__device__ float    g_thresh;

// ---------------- PTX helpers (base ISA only) ----------------
__device__ __forceinline__ uint32_t smem_u32(const void* p) {
    uint32_t a;
    asm("{ .reg .u64 t; cvta.to.shared.u64 t, %1; cvt.u32.u64 %0, t; }" : "=r"(a) : "l"(p));
    return a;
}
__device__ __forceinline__ void cp16(uint32_t s, const void* g) {
    asm volatile("cp.async.cg.shared.global [%0], [%1], 16;" :: "r"(s), "l"(g));
}
__device__ __forceinline__ void cp_commit() { asm volatile("cp.async.commit_group;" ::: "memory"); }
__device__ __forceinline__ void cp_wait1()  { asm volatile("cp.async.wait_group 1;" ::: "memory"); }

__device__ __forceinline__ void ldsm4(uint32_t& r0, uint32_t& r1, uint32_t& r2, uint32_t& r3,
                                      uint32_t addr) {
    asm volatile("ldmatrix.sync.aligned.m8n8.x4.shared.b16 {%0,%1,%2,%3}, [%4];"
                 : "=r"(r0), "=r"(r1), "=r"(r2), "=r"(r3) : "r"(addr));
}

__device__ __forceinline__ void mma16816(float* c, const uint32_t* a, uint32_t b0, uint32_t b1) {
    asm volatile(
        "mma.sync.aligned.m16n8k16.row.col.f32.f16.f16.f32 "
        "{%0,%1,%2,%3}, {%4,%5,%6,%7}, {%8,%9}, {%0,%1,%2,%3};"
        : "+f"(c[0]), "+f"(c[1]), "+f"(c[2]), "+f"(c[3])
        : "r"(a[0]), "r"(a[1]), "r"(a[2]), "r"(a[3]), "r"(b0), "r"(b1));
}

// ---------------- selection: exact order statistic of |w| bits ----------------
__global__ void zero_kernel() {
    int i = blockIdx.x * blockDim.x + threadIdx.x;
    int st = gridDim.x * blockDim.x;
    for (int j = i; j < 8192; j += st) g_hist1[j] = 0;
    for (int j = i; j < 262144; j += st) g_hist2[j] = 0;
}

__global__ void hist1_kernel(const float4* __restrict__ w, int n4) {
    __shared__ unsigned sh[8192];
    for (int i = threadIdx.x; i < 8192; i += blockDim.x) sh[i] = 0;
    __syncthreads();
    int idx = blockIdx.x * blockDim.x + threadIdx.x;
    int stride = gridDim.x * blockDim.x;
    for (int i = idx; i < n4; i += stride) {
        float4 v = w[i];
        atomicAdd(&sh[(__float_as_uint(v.x) & 0x7FFFFFFFu) >> 18], 1u);
        atomicAdd(&sh[(__float_as_uint(v.y) & 0x7FFFFFFFu) >> 18], 1u);
        atomicAdd(&sh[(__float_as_uint(v.z) & 0x7FFFFFFFu) >> 18], 1u);
        atomicAdd(&sh[(__float_as_uint(v.w) & 0x7FFFFFFFu) >> 18], 1u);
    }
    __syncthreads();
    for (int i = threadIdx.x; i < 8192; i += blockDim.x) {
        unsigned c = sh[i];
        if (c) atomicAdd(&g_hist1[i], c);
    }
}

__global__ void scan1_kernel(unsigned rank) {
    __shared__ unsigned partial[1024];
    int t = threadIdx.x;
    unsigned v[8];
    unsigned s = 0;
#pragma unroll
    for (int i = 0; i < 8; i++) { v[i] = g_hist1[t * 8 + i]; s += v[i]; }
    partial[t] = s;
    __syncthreads();
    for (int ofs = 1; ofs < 1024; ofs <<= 1) {
        unsigned x = (t >= ofs) ? partial[t - ofs] : 0u;
        __syncthreads();
        partial[t] += x;
        __syncthreads();
    }
    unsigned base = partial[t] - s;  // exclusive prefix
    if (rank >= base && rank < partial[t]) {
        unsigned cum = base;
#pragma unroll
        for (int i = 0; i < 8; i++) {
            if (rank < cum + v[i]) { g_selP = (unsigned)(t * 8 + i); g_selBase = cum; break; }
            cum += v[i];
        }
    }
}

__global__ void hist2_kernel(const float4* __restrict__ w, int n4) {
    unsigned P = g_selP;
    int idx = blockIdx.x * blockDim.x + threadIdx.x;
    int stride = gridDim.x * blockDim.x;
    for (int i = idx; i < n4; i += stride) {
        float4 v = w[i];
        unsigned b;
        b = __float_as_uint(v.x) & 0x7FFFFFFFu; if ((b >> 18) == P) atomicAdd(&g_hist2[b & 0x3FFFFu], 1u);
        b = __float_as_uint(v.y) & 0x7FFFFFFFu; if ((b >> 18) == P) atomicAdd(&g_hist2[b & 0x3FFFFu], 1u);
        b = __float_as_uint(v.z) & 0x7FFFFFFFu; if ((b >> 18) == P) atomicAdd(&g_hist2[b & 0x3FFFFu], 1u);
        b = __float_as_uint(v.w) & 0x7FFFFFFFu; if ((b >> 18) == P) atomicAdd(&g_hist2[b & 0x3FFFFu], 1u);
    }
}

__global__ void scan2_kernel(unsigned rank) {
    __shared__ unsigned partial[1024];
    int t = threadIdx.x;
    unsigned s = 0;
    for (int i = 0; i < 256; i++) s += g_hist2[t * 256 + i];
    partial[t] = s;
    __syncthreads();
    for (int ofs = 1; ofs < 1024; ofs <<= 1) {
        unsigned x = (t >= ofs) ? partial[t - ofs] : 0u;
        __syncthreads();
        partial[t] += x;
        __syncthreads();
    }
    unsigned base = partial[t] - s;
    unsigned rl = rank - g_selBase;
    if (rl >= base && rl < partial[t]) {
        unsigned cum = base;
        for (int i = 0; i < 256; i++) {
            unsigned c = g_hist2[t * 256 + i];
            if (rl < cum + c) {
                g_thresh = __uint_as_float((g_selP << 18) | (unsigned)(t * 256 + i));
                break;
            }
            cum += c;
        }
    }
}

// ---------------- fused fp16 conversion (X then W, one grid) ----------------
#define XBLK 1184
#define WBLK 592
__global__ void conv_xw_kernel(const float4* __restrict__ x, const float4* __restrict__ w) {
    if (blockIdx.x < XBLK) {
        int idx = blockIdx.x * blockDim.x + threadIdx.x;
        int stride = XBLK * blockDim.x;
        uint2* out = reinterpret_cast<uint2*>(g_X16);
        const int n4 = (M_DIM * K_DIM) / 4;
        for (int i = idx; i < n4; i += stride) {
            float4 v = x[i];
            __half2 h0 = __floats2half2_rn(v.x, v.y);
            __half2 h1 = __floats2half2_rn(v.z, v.w);
            uint2 o;
            o.x = *reinterpret_cast<unsigned*>(&h0);
            o.y = *reinterpret_cast<unsigned*>(&h1);
            out[i] = o;
        }
    } else {
        float t = g_thresh;
        int idx = (blockIdx.x - XBLK) * blockDim.x + threadIdx.x;
        int stride = WBLK * blockDim.x;
        uint2* out = reinterpret_cast<uint2*>(g_W16);
        const int n4 = (N_DIM * K_DIM) / 4;
        for (int i = idx; i < n4; i += stride) {
            float4 v = w[i];
            float a0 = (fabsf(v.x) >= t) ? v.x : 0.0f;
            float a1 = (fabsf(v.y) >= t) ? v.y : 0.0f;
            float a2 = (fabsf(v.z) >= t) ? v.z : 0.0f;
            float a3 = (fabsf(v.w) >= t) ? v.w : 0.0f;
            __half2 h0 = __floats2half2_rn(a0, a1);
            __half2 h1 = __floats2half2_rn(a2, a3);
            uint2 o;
            o.x = *reinterpret_cast<unsigned*>(&h0);
            o.y = *reinterpret_cast<unsigned*>(&h1);
            out[i] = o;
        }
    }
}

// ---- GEMM: 128x128 CTA tile, 4 warps (64x64 warp tiles), 3-stage cp.async, occ=2,
// ----       single __syncthreads per K-iteration (wait -> sync -> compute -> load-next)
#define BM 128
#define BN 128
#define BKH 64                      // K halves per stage (128 B rows -> SW128)
#define NK (K_DIM / BKH)            // 64
#define STG 3
#define OP_BYTES (BM * 128)         // 16384
#define STAGE_B (2 * OP_BYTES)      // 32768
#define SMEM_GEMM (STG * STAGE_B)   // 98304 per CTA (x2 CTAs = 192K < 228K)
#define NTHR 128

__device__ __forceinline__ void load_stage(uint32_t st, int m0, int n0, int kidx, int tid) {
    const __half* Xp = g_X16 + (size_t)m0 * K_DIM + (size_t)kidx * BKH;
    const __half* Wp = g_W16 + (size_t)n0 * K_DIM + (size_t)kidx * BKH;
#pragma unroll
    for (int i = 0; i < 8; i++) {
        int c = tid + i * NTHR;          // 0..1023 (128 rows x 8 chunks)
        int row = c >> 3, ci = c & 7;
        cp16(st + row * 128 + ((ci ^ (row & 7)) << 4), Xp + (size_t)row * K_DIM + ci * 8);
    }
#pragma unroll
    for (int i = 0; i < 8; i++) {
        int c = tid + i * NTHR;
        int row = c >> 3, ci = c & 7;
        cp16(st + OP_BYTES + row * 128 + ((ci ^ (row & 7)) << 4), Wp + (size_t)row * K_DIM + ci * 8);
    }
}

__global__ void __launch_bounds__(NTHR, 2) gemm_kernel(const float* __restrict__ bias,
                                                       float* __restrict__ out) {
    extern __shared__ char smraw[];
    const uint32_t sbase = smem_u32(smraw);
    const int tid = threadIdx.x;
    const int wid = tid >> 5;
    const int lane = tid & 31;
    const int warp_m = wid >> 1;     // 0..1 (64 rows each)
    const int warp_n = wid & 1;      // 0..1 (64 cols each)
    const int m0 = blockIdx.y * BM;
    const int n0 = blockIdx.x * BN;

    float acc[4][8][4];
#pragma unroll
    for (int i = 0; i < 4; i++)
#pragma unroll
        for (int j = 0; j < 8; j++)
#pragma unroll
            for (int k = 0; k < 4; k++) acc[i][j][k] = 0.0f;

    // ldmatrix lane geometry
    const int g  = lane >> 3;             // 0..3
    const int lr = lane & 7;
    const int r16 = ((g & 1) << 3) + lr;  // row within a 16-row tile
    const int kg  = g >> 1;               // 16B chunk parity within k16

    // prologue: stages 0,1 in flight
    load_stage(sbase + 0 * STAGE_B, m0, n0, 0, tid); cp_commit();
    load_stage(sbase + 1 * STAGE_B, m0, n0, 1, tid); cp_commit();

    for (int ki = 0; ki < NK; ki++) {
        cp_wait1();          // own groups: stage ki arrived (<=1 group outstanding)
        __syncthreads();     // all warps' portions visible; also closes iter ki-1 reads

        const uint32_t sA = sbase + (uint32_t)(ki % STG) * STAGE_B;
        const uint32_t sB = sA + OP_BYTES;

#pragma unroll
        for (int ks = 0; ks < 4; ks++) {            // 4 x k16 per stage
            const int chunk = ks * 2 + kg;           // 16B chunk index 0..7
            uint32_t a[4][4], b[4][4];
#pragma unroll
            for (int mt = 0; mt < 4; mt++) {
                int row = warp_m * 64 + mt * 16 + r16;
                uint32_t ad = sA + row * 128 + ((chunk ^ (row & 7)) << 4);
                ldsm4(a[mt][0], a[mt][1], a[mt][2], a[mt][3], ad);
            }
#pragma unroll
            for (int bt = 0; bt < 4; bt++) {
                int row = warp_n * 64 + bt * 16 + r16;
                uint32_t ad = sB + row * 128 + ((chunk ^ (row & 7)) << 4);
                ldsm4(b[bt][0], b[bt][1], b[bt][2], b[bt][3], ad);
            }
#pragma unroll
            for (int mt = 0; mt < 4; mt++)
#pragma unroll
                for (int nt = 0; nt < 8; nt++) {
                    int bt = nt >> 1, od = nt & 1;
                    mma16816(acc[mt][nt], a[mt], b[bt][od], b[bt][2 + od]);
                }
        }

        // load stage ki+2 AFTER compute: its buffer (ki+2)%3 == (ki-1)%3, whose readers
        // (iteration ki-1) are provably done once any warp passed this iteration's sync.
        if (ki + 2 < NK) load_stage(sbase + ((ki + 2) % STG) * STAGE_B, m0, n0, ki + 2, tid);
        cp_commit();
    }

    // epilogue
    const int qr = lane >> 2, qc = lane & 3;
#pragma unroll
    for (int nt = 0; nt < 8; nt++) {
        int col = n0 + warp_n * 64 + nt * 8 + qc * 2;
        float2 bb = *reinterpret_cast<const float2*>(bias + col);
#pragma unroll
        for (int mt = 0; mt < 4; mt++) {
            int r0 = m0 + warp_m * 64 + mt * 16 + qr;
            float2 v0, v1;
            v0.x = acc[mt][nt][0] + bb.x;  v0.y = acc[mt][nt][1] + bb.y;
            v1.x = acc[mt][nt][2] + bb.x;  v1.y = acc[mt][nt][3] + bb.y;
            *reinterpret_cast<float2*>(out + (size_t)r0 * N_DIM + col) = v0;
            *reinterpret_cast<float2*>(out + (size_t)(r0 + 8) * N_DIM + col) = v1;
        }
    }
}

// ---------------- launch ----------------
extern "C" void kernel_launch(void* const* d_in, const int* in_sizes, int n_in,
                              void* d_out, int out_size) {
    (void)in_sizes; (void)n_in; (void)out_size;
    const float4* x4 = reinterpret_cast<const float4*>(d_in[0]);
    const float4* w4 = reinterpret_cast<const float4*>(d_in[1]);
    const float*  bias = reinterpret_cast<const float*>(d_in[2]);
    float* out = reinterpret_cast<float*>(d_out);

    const int NW4 = (N_DIM * K_DIM) / 4;

    cudaFuncSetAttribute(gemm_kernel, cudaFuncAttributeMaxDynamicSharedMemorySize, SMEM_GEMM);

    zero_kernel<<<512, 256>>>();
    hist1_kernel<<<1184, 256>>>(w4, NW4);
    scan1_kernel<<<1, 1024>>>(RANK_K);
    hist2_kernel<<<1184, 256>>>(w4, NW4);
    scan2_kernel<<<1, 1024>>>(RANK_K);
    conv_xw_kernel<<<XBLK + WBLK, 256>>>(x4, w4);
    gemm_kernel<<<dim3(N_DIM / BN, M_DIM / BM), NTHR, SMEM_GEMM>>>(bias, out);
}